// round 16
// baseline (speedup 1.0000x reference)
#include <cuda_runtime.h>
#include <cuda_fp16.h>
#include <math.h>
#include <stdint.h>

#define BSZ   8192
#define DIN   1024
#define DH    1024
#define HD    256
#define DP    1365
#define DPAD  1376
#define GN    4096
#define PLANE (BSZ*DH)

#define BM 128
#define THR 256
#define SROW 80                      // smem row stride BYTES (40 halves)
#define A_BYTES 10240                // 128 rows * 80B
#define STAGE_BYTES 20480
#define NSTAGE 4
#define SMEMSZ (NSTAGE*STAGE_BYTES)  // 81920 -> 2 CTAs/SM

#define G_KT 40                      // K=1280 / 32
#define U_KT 32
#define D_KT 43
#define G_NT 32
#define U_NT 22
#define D_NT 8

#define UB_TOT ((size_t)U_NT * U_KT * 4096)   // 2883584
#define DB_TOT ((size_t)D_NT * D_KT * 4096)   // 1409024

// Scratch (static device globals — allocation-free rule)
__device__ __half g_xnorm[(size_t)BSZ * DIN];
__device__ __half g_hr[(size_t)BSZ * DH];
__device__ __half g_gates[(size_t)BSZ * GN];     // fp16
__device__ __half g_htnorm[(size_t)BSZ * DH];
__device__ __half g_act[(size_t)BSZ * DPAD];
__device__ float  g_bias[GN];
// tile-linear B images: [tile][128 n-rows][32 k halves], tile = nt*KT + kt
__device__ __half g_Bg[(size_t)G_NT * G_KT * 4096];
__device__ __half g_Bup[(size_t)U_NT * U_KT * 4096];
__device__ __half g_Bd[(size_t)D_NT * D_KT * 4096];

// ---------------- helpers ----------------
__device__ __forceinline__ void mma16(float* c, const unsigned* a, const unsigned* b) {
    asm volatile(
        "mma.sync.aligned.m16n8k16.row.col.f32.f16.f16.f32 "
        "{%0,%1,%2,%3}, {%4,%5,%6,%7}, {%8,%9}, {%0,%1,%2,%3};"
        : "+f"(c[0]), "+f"(c[1]), "+f"(c[2]), "+f"(c[3])
        : "r"(a[0]), "r"(a[1]), "r"(a[2]), "r"(a[3]), "r"(b[0]), "r"(b[1]));
}
__device__ __forceinline__ void cp16(uint32_t dst, const void* src) {
    asm volatile("cp.async.cg.shared.global [%0], [%1], 16;\n" :: "r"(dst), "l"(src));
}
#define CP_COMMIT asm volatile("cp.async.commit_group;\n" ::: "memory")
#define CP_WAIT(n) asm volatile("cp.async.wait_group %0;\n" :: "n"(n) : "memory")
#define LDSM4(R, addr) \
    asm volatile("ldmatrix.sync.aligned.m8n8.x4.shared.b16 {%0,%1,%2,%3}, [%4];" \
        : "=r"((R)[0]), "=r"((R)[1]), "=r"((R)[2]), "=r"((R)[3]) : "r"(addr))

// ---------------- repack: gates B image + fused bias -----------------------
__global__ __launch_bounds__(256) void repack_gb(
    const float* __restrict__ Wz, const float* __restrict__ Wi,
    const float* __restrict__ Wf, const float* __restrict__ Wo,
    const float* __restrict__ Rz, const float* __restrict__ Ri,
    const float* __restrict__ Rf, const float* __restrict__ Ro,
    const float* __restrict__ bz, const float* __restrict__ bi,
    const float* __restrict__ bf, const float* __restrict__ bo,
    const float* __restrict__ rbz, const float* __restrict__ rbi,
    const float* __restrict__ rbf, const float* __restrict__ rbo)
{
    size_t idx = (size_t)blockIdx.x * 256 + threadIdx.x;
    if (idx >= (size_t)G_NT * G_KT * 4096) return;
    if (idx < GN) {
        int c = (int)idx, g = c >> 10, cl = c & 1023;
        const float* b  = (g == 0) ? bz  : (g == 1) ? bi  : (g == 2) ? bf  : bo;
        const float* rb = (g == 0) ? rbz : (g == 1) ? rbi : (g == 2) ? rbf : rbo;
        g_bias[c] = b[cl] + rb[cl];
    }
    int tile = (int)(idx >> 12), r = (int)(idx & 4095);
    int nloc = r >> 5, kloc = r & 31;
    int nt = tile / G_KT, kt = tile % G_KT;
    int n = nt * 128 + nloc, k = kt * 32 + kloc, gate = n >> 10;
    float v;
    if (k < 1024) {
        const float* W = (gate == 0) ? Wz : (gate == 1) ? Wi : (gate == 2) ? Wf : Wo;
        v = W[(size_t)k * DH + (n & 1023)];
    } else {
        const float* R = (gate == 0) ? Rz : (gate == 1) ? Ri : (gate == 2) ? Rf : Ro;
        v = R[((n >> 8) & 3) * 65536 + (k - 1024) * 256 + (n & 255)];
    }
    g_Bg[idx] = __float2half_rn(v);
}

// ---------------- LayerNorm (fp16 out) + h rounding, fused ----------------
__global__ __launch_bounds__(256) void lnh_kernel(const float* __restrict__ x,
                                                  const float* __restrict__ w,
                                                  const float* __restrict__ b,
                                                  const float* __restrict__ hp)
{
    int blk = blockIdx.x, tid = threadIdx.x;
    if (blk >= BSZ) {
        int idx = (blk - BSZ) * 256 + tid;
        float4 v = ((const float4*)hp)[idx];
        ((__half2*)g_hr)[idx * 2]     = __floats2half2_rn(v.x, v.y);
        ((__half2*)g_hr)[idx * 2 + 1] = __floats2half2_rn(v.z, v.w);
        return;
    }
    int row = blk;
    float4 v = *(const float4*)(x + (size_t)row * DIN + tid * 4);
    float s = v.x + v.y + v.z + v.w;
    float ss = v.x*v.x + v.y*v.y + v.z*v.z + v.w*v.w;
    __shared__ float r0[8], r1[8];
    unsigned lane = tid & 31, wid = tid >> 5;
    #pragma unroll
    for (int o = 16; o; o >>= 1) {
        s += __shfl_down_sync(0xffffffffu, s, o);
        ss += __shfl_down_sync(0xffffffffu, ss, o);
    }
    if (!lane) { r0[wid] = s; r1[wid] = ss; }
    __syncthreads();
    float S = 0.f, SS = 0.f;
    #pragma unroll
    for (int i = 0; i < 8; ++i) { S += r0[i]; SS += r1[i]; }
    float mean = S * (1.f / DIN);
    float rstd = rsqrtf(SS * (1.f / DIN) - mean * mean + 1e-5f);
    float4 wv = *(const float4*)(w + tid * 4);
    float4 bv = *(const float4*)(b + tid * 4);
    __half2* dst = (__half2*)(g_xnorm + (size_t)row * DIN) + tid * 2;
    dst[0] = __floats2half2_rn((v.x-mean)*rstd*wv.x + bv.x, (v.y-mean)*rstd*wv.y + bv.y);
    dst[1] = __floats2half2_rn((v.z-mean)*rstd*wv.z + bv.z, (v.w-mean)*rstd*wv.w + bv.w);
}

// ---------------- cell + GroupNorm (fp16 gates in, fp16 htnorm out) --------
__global__ __launch_bounds__(256) void cell_kernel(
    const float* __restrict__ cp, const float* __restrict__ np,
    const float* __restrict__ mp,
    const float* __restrict__ gnw, const float* __restrict__ gnb,
    float* __restrict__ ht_o, float* __restrict__ ct_o,
    float* __restrict__ nt_o, float* __restrict__ mt_o)
{
    int bh = blockIdx.x, b = bh >> 2, h = bh & 3, d = threadIdx.x;
    size_t idx = (size_t)b * DH + h * 256 + d;
    size_t gb = (size_t)b * GN + h * 256 + d;
    float z  = __half2float(g_gates[gb]);
    float i_ = __half2float(g_gates[gb + 1024]);
    float f_ = __half2float(g_gates[gb + 2048]);
    float o_ = __half2float(g_gates[gb + 3072]);
    float mpv = mp[idx], cpv = cp[idx], npv = np[idx];
    float zt = tanhf(z);
    float ot = 1.f / (1.f + expf(-o_));
    float fm = f_ + mpv;
    float mt = fmaxf(fm, i_);
    float it = expf(i_ - mt), ft = expf(fm - mt);
    float ct = ft * cpv + it * zt;
    float nt = ft * npv + it;
    float ht = ot * (ct / (nt + 1e-13f));
    ht_o[idx] = ht; ct_o[idx] = ct; nt_o[idx] = nt; mt_o[idx] = mt;
    float s = ht, ss = ht * ht;
    __shared__ float r0[8], r1[8];
    unsigned lane = d & 31, wid = d >> 5;
    #pragma unroll
    for (int o = 16; o; o >>= 1) {
        s += __shfl_down_sync(0xffffffffu, s, o);
        ss += __shfl_down_sync(0xffffffffu, ss, o);
    }
    if (!lane) { r0[wid] = s; r1[wid] = ss; }
    __syncthreads();
    float S = 0.f, SS = 0.f;
    #pragma unroll
    for (int i = 0; i < 8; ++i) { S += r0[i]; SS += r1[i]; }
    float mean = S * (1.f / 256.f);
    float rstd = rsqrtf(SS * (1.f / 256.f) - mean * mean + 1e-5f);
    int c = h * 256 + d;
    g_htnorm[idx] = __float2half_rn((ht - mean) * rstd * gnw[c] + gnb[c]);
}

// ---------------- GEMM: fp16, BM=128 x BN=128, 2 CTAs/SM, batched LDSM -----
// MODE 0 = gates (fp16 out) + co-scheduled Wup/Wd repack (e0=Wup, e1=Wdown)
// MODE 1 = up+GeGLU (e0=bup)   MODE 2 = down+residual (e0=x, e1=bdown)
template<int MODE>
__global__ __launch_bounds__(THR, 2) void gemm_ls(const float* __restrict__ e0,
                                                  const float* __restrict__ e1,
                                                  float* __restrict__ outp)
{
    constexpr int KT  = (MODE == 0) ? G_KT : (MODE == 1) ? U_KT : D_KT;
    constexpr int AST = (MODE == 2) ? DPAD : DIN;   // halves per A row

    extern __shared__ char smem[];
    const uint32_t sb = (uint32_t)__cvta_generic_to_shared(smem);

    const int tid = threadIdx.x, lane = tid & 31, wid = tid >> 5;
    const int wm = wid & 3, wn = wid >> 2;          // 4m x 2n warp grid
    const int grp = lane >> 2, tig = lane & 3;
    const int nt = blockIdx.x, row0 = blockIdx.y * BM;

    const uint32_t aBase = (uint32_t)((wm * 32 + (lane & 15)) * SROW + ((lane >> 4) << 4));
    const uint32_t bLane = (uint32_t)(((((lane >> 4) << 3) + (lane & 7)) * SROW) +
                                      (((lane >> 3) & 1) << 4));
    uint32_t bOff[4];
    #pragma unroll
    for (int p = 0; p < 4; ++p) {
        int nrow = (MODE == 1)
            ? ((p < 2) ? wn * 32 + p * 16 : 64 + wn * 32 + (p - 2) * 16)
            : wn * 64 + p * 16;
        bOff[p] = A_BYTES + (uint32_t)(nrow * SROW) + bLane;
    }

    const __half* Abase = (MODE == 0) ? g_xnorm + (size_t)row0 * DIN
                        : (MODE == 1) ? g_htnorm + (size_t)row0 * DH
                                      : g_act + (size_t)row0 * DPAD;
    const __half* Ahr = (MODE == 0)
        ? g_hr + (size_t)row0 * DH + ((nt >> 1) & 3) * HD : (const __half*)0;
    const __half* Bimg = (MODE == 0) ? g_Bg : (MODE == 1) ? g_Bup : g_Bd;

    auto loadTile = [&](int kt) {
        uint32_t stg = sb + (uint32_t)(kt & 3) * STAGE_BYTES;
        const __half* Asrc = (MODE == 0 && kt >= 32)
            ? Ahr + (kt - 32) * 32 : Abase + kt * 32;
        #pragma unroll
        for (int i = 0; i < 2; ++i) {
            int q = tid + i * THR, r = q >> 2, c = q & 3;
            cp16(stg + (uint32_t)(r * SROW + c * 16), Asrc + (size_t)r * AST + c * 8);
        }
        const __half* Bsrc = Bimg + ((size_t)nt * KT + kt) * 4096;
        #pragma unroll
        for (int i = 0; i < 2; ++i) {
            int q = tid + i * THR;
            cp16(stg + A_BYTES + (uint32_t)((q >> 2) * SROW + (q & 3) * 16), Bsrc + q * 8);
        }
    };

    float acc[2][8][4];
    #pragma unroll
    for (int mi = 0; mi < 2; ++mi)
        #pragma unroll
        for (int ni = 0; ni < 8; ++ni)
            #pragma unroll
            for (int q = 0; q < 4; ++q) acc[mi][ni][q] = 0.f;

    loadTile(0); CP_COMMIT;
    loadTile(1); CP_COMMIT;
    loadTile(2); CP_COMMIT;

    for (int t = 0; t < KT; ++t) {
        if (t <= KT - 3)      { CP_WAIT(2); }
        else if (t == KT - 2) { CP_WAIT(1); }
        else                  { CP_WAIT(0); }
        __syncthreads();
        if (t + 3 < KT) { loadTile(t + 3); CP_COMMIT; }

        uint32_t stg = sb + (uint32_t)(t & 3) * STAGE_BYTES;
        unsigned af[2][2][4], bf[2][8][2];
        #pragma unroll
        for (int ks = 0; ks < 2; ++ks) {
            uint32_t kb = (uint32_t)(ks * 32);
            LDSM4(af[ks][0], stg + aBase + kb);
            LDSM4(af[ks][1], stg + aBase + 16 * SROW + kb);
            LDSM4(&bf[ks][0][0], stg + bOff[0] + kb);
            LDSM4(&bf[ks][2][0], stg + bOff[1] + kb);
            LDSM4(&bf[ks][4][0], stg + bOff[2] + kb);
            LDSM4(&bf[ks][6][0], stg + bOff[3] + kb);
        }
        #pragma unroll
        for (int ks = 0; ks < 2; ++ks)
            #pragma unroll
            for (int mi = 0; mi < 2; ++mi)
                #pragma unroll
                for (int ni = 0; ni < 8; ++ni)
                    mma16(acc[mi][ni], af[ks][mi], bf[ks][ni]);
    }
    __syncthreads();

    if (MODE == 0) {
        #pragma unroll
        for (int mi = 0; mi < 2; ++mi) {
            int r = row0 + wm * 32 + mi * 16 + grp;
            #pragma unroll
            for (int ni = 0; ni < 8; ++ni) {
                int c = nt * 128 + wn * 64 + ni * 8 + tig * 2;
                float b0 = g_bias[c], b1 = g_bias[c + 1];
                *(__half2*)&g_gates[(size_t)r * GN + c] =
                    __floats2half2_rn(acc[mi][ni][0] + b0, acc[mi][ni][1] + b1);
                *(__half2*)&g_gates[(size_t)(r + 8) * GN + c] =
                    __floats2half2_rn(acc[mi][ni][2] + b0, acc[mi][ni][3] + b1);
            }
        }
        // ---- co-scheduled repack of Wup (e0) and Wdown (e1) B images ----
        // Runs in the retirement shadow of other CTAs' mainloops.
        {
            const size_t stride = (size_t)gridDim.x * gridDim.y * THR;
            size_t base = ((size_t)(blockIdx.y * gridDim.x + blockIdx.x)) * THR + tid;
            for (size_t w = base; w < UB_TOT + DB_TOT; w += stride) {
                if (w < UB_TOT) {
                    int tile = (int)(w >> 12), rr = (int)(w & 4095);
                    int nloc = rr >> 5, kloc = rr & 31;
                    int unt = tile >> 5, ukt = tile & 31;     // U_KT = 32
                    int half = nloc >> 6;
                    int outc = unt * 64 + (nloc & 63);
                    int k = ukt * 32 + kloc;
                    float v = 0.f;
                    if (outc < DP) v = e0[(size_t)k * (2 * DP) + outc + half * DP];
                    g_Bup[w] = __float2half_rn(v);
                } else {
                    size_t w2 = w - UB_TOT;
                    int tile = (int)(w2 >> 12), rr = (int)(w2 & 4095);
                    int nloc = rr >> 5, kloc = rr & 31;
                    int dnt = tile / D_KT, dkt = tile % D_KT;
                    int n = dnt * 128 + nloc, k = dkt * 32 + kloc;
                    g_Bd[w2] = __float2half_rn((k < DP) ? e1[(size_t)k * DIN + n] : 0.f);
                }
            }
        }
    } else if (MODE == 2) {
        #pragma unroll
        for (int mi = 0; mi < 2; ++mi) {
            int r = row0 + wm * 32 + mi * 16 + grp;
            #pragma unroll
            for (int ni = 0; ni < 8; ++ni) {
                int c = nt * 128 + wn * 64 + ni * 8 + tig * 2;
                float b0 = e1[c], b1 = e1[c + 1];
                float2 x0 = *(const float2*)&e0[(size_t)r * DIN + c];
                float2 x1 = *(const float2*)&e0[(size_t)(r + 8) * DIN + c];
                float2 v0 = {acc[mi][ni][0] + b0 + x0.x, acc[mi][ni][1] + b1 + x0.y};
                float2 v1 = {acc[mi][ni][2] + b0 + x1.x, acc[mi][ni][3] + b1 + x1.y};
                *(float2*)&outp[(size_t)r * DIN + c]       = v0;
                *(float2*)&outp[(size_t)(r + 8) * DIN + c] = v1;
            }
        }
    } else {
        // MODE 1: acc[mi][j] = S, acc[mi][j+4] = G of the SAME output column
        #pragma unroll
        for (int mi = 0; mi < 2; ++mi) {
            int rb = row0 + wm * 32 + mi * 16 + grp;
            #pragma unroll
            for (int j = 0; j < 4; ++j) {
                int cc = nt * 64 + wn * 32 + j * 8 + tig * 2;
                #pragma unroll
                for (int h = 0; h < 2; ++h) {
                    int row = rb + h * 8;
                    #pragma unroll
                    for (int jj = 0; jj < 2; ++jj) {
                        int c2 = cc + jj;
                        if (c2 < DPAD) {
                            float v = 0.f;
                            if (c2 < DP) {
                                float sv = acc[mi][j][h * 2 + jj] + e0[c2];
                                float gv = acc[mi][j + 4][h * 2 + jj] + e0[c2 + DP];
                                float ge = 0.5f * gv * (1.f + erff(gv * 0.70710678118654752f));
                                v = sv * ge;
                            }
                            g_act[(size_t)row * DPAD + c2] = __float2half_rn(v);
                        }
                    }
                }
            }
        }
    }
}

// ---------------- launch ----------------
extern "C" void kernel_launch(void* const* d_in, const int* in_sizes, int n_in,
                              void* d_out, int out_size)
{
    const float* x      = (const float*)d_in[0];
    const float* h_prev = (const float*)d_in[1];
    const float* c_prev = (const float*)d_in[2];
    const float* n_prev = (const float*)d_in[3];
    const float* m_prev = (const float*)d_in[4];
    const float* ln_w   = (const float*)d_in[5];
    const float* ln_b   = (const float*)d_in[6];
    const float* Wz = (const float*)d_in[7];
    const float* bz = (const float*)d_in[8];
    const float* Wi = (const float*)d_in[9];
    const float* bi = (const float*)d_in[10];
    const float* Wf = (const float*)d_in[11];
    const float* bf = (const float*)d_in[12];
    const float* Wo = (const float*)d_in[13];
    const float* bo = (const float*)d_in[14];
    const float* Rz  = (const float*)d_in[15];
    const float* rbz = (const float*)d_in[16];
    const float* Ri  = (const float*)d_in[17];
    const float* rbi = (const float*)d_in[18];
    const float* Rf  = (const float*)d_in[19];
    const float* rbf = (const float*)d_in[20];
    const float* Ro  = (const float*)d_in[21];
    const float* rbo = (const float*)d_in[22];
    const float* gn_w = (const float*)d_in[23];
    const float* gn_b = (const float*)d_in[24];
    const float* Wup  = (const float*)d_in[25];
    const float* bup  = (const float*)d_in[26];
    const float* Wdown = (const float*)d_in[27];
    const float* bdown = (const float*)d_in[28];

    float* out  = (float*)d_out;
    float* y_o  = out;
    float* ht_o = out + (size_t)PLANE;
    float* ct_o = out + (size_t)2 * PLANE;
    float* nt_o = out + (size_t)3 * PLANE;
    float* mt_o = out + (size_t)4 * PLANE;

    cudaFuncSetAttribute(gemm_ls<0>, cudaFuncAttributeMaxDynamicSharedMemorySize, SMEMSZ);
    cudaFuncSetAttribute(gemm_ls<1>, cudaFuncAttributeMaxDynamicSharedMemorySize, SMEMSZ);
    cudaFuncSetAttribute(gemm_ls<2>, cudaFuncAttributeMaxDynamicSharedMemorySize, SMEMSZ);

    repack_gb<<<(G_NT * G_KT * 4096 + 255) / 256, 256>>>(
        Wz, Wi, Wf, Wo, Rz, Ri, Rf, Ro,
        bz, bi, bf, bo, rbz, rbi, rbf, rbo);
    lnh_kernel<<<BSZ + PLANE / 1024, 256>>>(x, ln_w, ln_b, h_prev);

    // gates GEMM also repacks Wup/Wdown in its CTA-retirement shadow
    gemm_ls<0><<<dim3(G_NT, BSZ / BM), THR, SMEMSZ>>>(Wup, Wdown, nullptr);

    cell_kernel<<<BSZ * 4, 256>>>(c_prev, n_prev, m_prev, gn_w, gn_b,
                                  ht_o, ct_o, nt_o, mt_o);

    gemm_ls<1><<<dim3(U_NT, BSZ / BM), THR, SMEMSZ>>>(bup, nullptr, nullptr);

    gemm_ls<2><<<dim3(D_NT, BSZ / BM), THR, SMEMSZ>>>(x, bdown, y_o);
}

// round 17
// speedup vs baseline: 1.0138x; 1.0138x over previous
#include <cuda_runtime.h>
#include <cuda_fp16.h>
#include <math.h>
#include <stdint.h>

#define BSZ   8192
#define DIN   1024
#define DH    1024
#define HD    256
#define DP    1365
#define DPAD  1376
#define GN    4096
#define PLANE (BSZ*DH)

#define BM 128
#define THR 256
#define SROW 80                      // smem row stride BYTES (40 halves)
#define A_BYTES 10240                // 128 rows * 80B
#define STAGE_BYTES 20480
#define NSTAGE 4
#define SMEMSZ (NSTAGE*STAGE_BYTES)  // 81920 -> 2 CTAs/SM

#define G_KT 40                      // K=1280 / 32
#define U_KT 32
#define D_KT 43
#define G_NT 32
#define U_NT 22
#define D_NT 8

// Scratch (static device globals — allocation-free rule)
__device__ __half g_xnorm[(size_t)BSZ * DIN];
__device__ __half g_hr[(size_t)BSZ * DH];
__device__ __half g_gates[(size_t)BSZ * GN];     // fp16
__device__ __half g_htnorm[(size_t)BSZ * DH];
__device__ __half g_act[(size_t)BSZ * DPAD];
__device__ float  g_bias[GN];
// tile-linear B images: [tile][128 n-rows][32 k halves], tile = nt*KT + kt
__device__ __half g_Bg[(size_t)G_NT * G_KT * 4096];
__device__ __half g_Bup[(size_t)U_NT * U_KT * 4096];
__device__ __half g_Bd[(size_t)D_NT * D_KT * 4096];

// ---------------- helpers ----------------
__device__ __forceinline__ void mma16(float* c, const unsigned* a, const unsigned* b) {
    asm volatile(
        "mma.sync.aligned.m16n8k16.row.col.f32.f16.f16.f32 "
        "{%0,%1,%2,%3}, {%4,%5,%6,%7}, {%8,%9}, {%0,%1,%2,%3};"
        : "+f"(c[0]), "+f"(c[1]), "+f"(c[2]), "+f"(c[3])
        : "r"(a[0]), "r"(a[1]), "r"(a[2]), "r"(a[3]), "r"(b[0]), "r"(b[1]));
}
__device__ __forceinline__ void cp16(uint32_t dst, const void* src) {
    asm volatile("cp.async.cg.shared.global [%0], [%1], 16;\n" :: "r"(dst), "l"(src));
}
#define CP_COMMIT asm volatile("cp.async.commit_group;\n" ::: "memory")
#define CP_WAIT(n) asm volatile("cp.async.wait_group %0;\n" :: "n"(n) : "memory")
#define LDSM4(R, addr) \
    asm volatile("ldmatrix.sync.aligned.m8n8.x4.shared.b16 {%0,%1,%2,%3}, [%4];" \
        : "=r"((R)[0]), "=r"((R)[1]), "=r"((R)[2]), "=r"((R)[3]) : "r"(addr))

// ---------------- repack: gates B image + fused bias -----------------------
__global__ __launch_bounds__(256) void repack_gb(
    const float* __restrict__ Wz, const float* __restrict__ Wi,
    const float* __restrict__ Wf, const float* __restrict__ Wo,
    const float* __restrict__ Rz, const float* __restrict__ Ri,
    const float* __restrict__ Rf, const float* __restrict__ Ro,
    const float* __restrict__ bz, const float* __restrict__ bi,
    const float* __restrict__ bf, const float* __restrict__ bo,
    const float* __restrict__ rbz, const float* __restrict__ rbi,
    const float* __restrict__ rbf, const float* __restrict__ rbo)
{
    size_t idx = (size_t)blockIdx.x * 256 + threadIdx.x;
    if (idx >= (size_t)G_NT * G_KT * 4096) return;
    if (idx < GN) {
        int c = (int)idx, g = c >> 10, cl = c & 1023;
        const float* b  = (g == 0) ? bz  : (g == 1) ? bi  : (g == 2) ? bf  : bo;
        const float* rb = (g == 0) ? rbz : (g == 1) ? rbi : (g == 2) ? rbf : rbo;
        g_bias[c] = b[cl] + rb[cl];
    }
    int tile = (int)(idx >> 12), r = (int)(idx & 4095);
    int nloc = r >> 5, kloc = r & 31;
    int nt = tile / G_KT, kt = tile % G_KT;
    int n = nt * 128 + nloc, k = kt * 32 + kloc, gate = n >> 10;
    float v;
    if (k < 1024) {
        const float* W = (gate == 0) ? Wz : (gate == 1) ? Wi : (gate == 2) ? Wf : Wo;
        v = W[(size_t)k * DH + (n & 1023)];
    } else {
        const float* R = (gate == 0) ? Rz : (gate == 1) ? Ri : (gate == 2) ? Rf : Ro;
        v = R[((n >> 8) & 3) * 65536 + (k - 1024) * 256 + (n & 255)];
    }
    g_Bg[idx] = __float2half_rn(v);
}

// up: rows 0-63 = S of cols nt*64+row, rows 64-127 = G of the same cols
__global__ __launch_bounds__(256) void repack_ub(const float* __restrict__ Wup)
{
    size_t idx = (size_t)blockIdx.x * 256 + threadIdx.x;
    if (idx >= (size_t)U_NT * U_KT * 4096) return;
    int tile = (int)(idx >> 12), r = (int)(idx & 4095);
    int nloc = r >> 5, kloc = r & 31;
    int nt = tile / U_KT, kt = tile % U_KT;
    int half = nloc >> 6;
    int out = nt * 64 + (nloc & 63);
    int k = kt * 32 + kloc;
    float v = 0.f;
    if (out < DP) v = Wup[(size_t)k * (2 * DP) + out + half * DP];
    g_Bup[idx] = __float2half_rn(v);
}

__global__ __launch_bounds__(256) void repack_db(const float* __restrict__ Wd)
{
    size_t idx = (size_t)blockIdx.x * 256 + threadIdx.x;
    if (idx >= (size_t)D_NT * D_KT * 4096) return;
    int tile = (int)(idx >> 12), r = (int)(idx & 4095);
    int nloc = r >> 5, kloc = r & 31;
    int nt = tile / D_KT, kt = tile % D_KT;
    int n = nt * 128 + nloc, k = kt * 32 + kloc;
    g_Bd[idx] = __float2half_rn((k < DP) ? Wd[(size_t)k * DIN + n] : 0.f);
}

// ---------------- LayerNorm (fp16 out) + h rounding, fused ----------------
__global__ __launch_bounds__(256) void lnh_kernel(const float* __restrict__ x,
                                                  const float* __restrict__ w,
                                                  const float* __restrict__ b,
                                                  const float* __restrict__ hp)
{
    int blk = blockIdx.x, tid = threadIdx.x;
    if (blk >= BSZ) {
        int idx = (blk - BSZ) * 256 + tid;
        float4 v = ((const float4*)hp)[idx];
        ((__half2*)g_hr)[idx * 2]     = __floats2half2_rn(v.x, v.y);
        ((__half2*)g_hr)[idx * 2 + 1] = __floats2half2_rn(v.z, v.w);
        return;
    }
    int row = blk;
    float4 v = *(const float4*)(x + (size_t)row * DIN + tid * 4);
    float s = v.x + v.y + v.z + v.w;
    float ss = v.x*v.x + v.y*v.y + v.z*v.z + v.w*v.w;
    __shared__ float r0[8], r1[8];
    unsigned lane = tid & 31, wid = tid >> 5;
    #pragma unroll
    for (int o = 16; o; o >>= 1) {
        s += __shfl_down_sync(0xffffffffu, s, o);
        ss += __shfl_down_sync(0xffffffffu, ss, o);
    }
    if (!lane) { r0[wid] = s; r1[wid] = ss; }
    __syncthreads();
    float S = 0.f, SS = 0.f;
    #pragma unroll
    for (int i = 0; i < 8; ++i) { S += r0[i]; SS += r1[i]; }
    float mean = S * (1.f / DIN);
    float rstd = rsqrtf(SS * (1.f / DIN) - mean * mean + 1e-5f);
    float4 wv = *(const float4*)(w + tid * 4);
    float4 bv = *(const float4*)(b + tid * 4);
    __half2* dst = (__half2*)(g_xnorm + (size_t)row * DIN) + tid * 2;
    dst[0] = __floats2half2_rn((v.x-mean)*rstd*wv.x + bv.x, (v.y-mean)*rstd*wv.y + bv.y);
    dst[1] = __floats2half2_rn((v.z-mean)*rstd*wv.z + bv.z, (v.w-mean)*rstd*wv.w + bv.w);
}

// ---------------- cell + GroupNorm (fast-math transcendentals) -------------
__global__ __launch_bounds__(256) void cell_kernel(
    const float* __restrict__ cp, const float* __restrict__ np,
    const float* __restrict__ mp,
    const float* __restrict__ gnw, const float* __restrict__ gnb,
    float* __restrict__ ht_o, float* __restrict__ ct_o,
    float* __restrict__ nt_o, float* __restrict__ mt_o)
{
    int bh = blockIdx.x, b = bh >> 2, h = bh & 3, d = threadIdx.x;
    size_t idx = (size_t)b * DH + h * 256 + d;
    size_t gb = (size_t)b * GN + h * 256 + d;
    float z  = __half2float(g_gates[gb]);
    float i_ = __half2float(g_gates[gb + 1024]);
    float f_ = __half2float(g_gates[gb + 2048]);
    float o_ = __half2float(g_gates[gb + 3072]);
    float mpv = mp[idx], cpv = cp[idx], npv = np[idx];
    // fast-math forms (MUFU ex2-based), ~1e-7 rel err << fp16 noise
    float zt = 1.f - __fdividef(2.f, __expf(2.f * z) + 1.f);
    float ot = __fdividef(1.f, 1.f + __expf(-o_));
    float fm = f_ + mpv;
    float mt = fmaxf(fm, i_);
    float it = __expf(i_ - mt), ft = __expf(fm - mt);
    float ct = ft * cpv + it * zt;
    float nt = ft * npv + it;
    float ht = ot * __fdividef(ct, nt + 1e-13f);
    ht_o[idx] = ht; ct_o[idx] = ct; nt_o[idx] = nt; mt_o[idx] = mt;
    float s = ht, ss = ht * ht;
    __shared__ float r0[8], r1[8];
    unsigned lane = d & 31, wid = d >> 5;
    #pragma unroll
    for (int o = 16; o; o >>= 1) {
        s += __shfl_down_sync(0xffffffffu, s, o);
        ss += __shfl_down_sync(0xffffffffu, ss, o);
    }
    if (!lane) { r0[wid] = s; r1[wid] = ss; }
    __syncthreads();
    float S = 0.f, SS = 0.f;
    #pragma unroll
    for (int i = 0; i < 8; ++i) { S += r0[i]; SS += r1[i]; }
    float mean = S * (1.f / 256.f);
    float rstd = rsqrtf(SS * (1.f / 256.f) - mean * mean + 1e-5f);
    int c = h * 256 + d;
    g_htnorm[idx] = __float2half_rn((ht - mean) * rstd * gnw[c] + gnb[c]);
}

// ---------------- GEMM: fp16, BM=128 x BN=128, 2 CTAs/SM, batched LDSM -----
// MODE 0 = gates (K=1280, bias epi, fp16 out), 1 = up+GeGLU, 2 = down+residual
template<int MODE>
__global__ __launch_bounds__(THR, 2) void gemm_ls(const float* __restrict__ e0,
                                                  const float* __restrict__ e1,
                                                  float* __restrict__ outp)
{
    constexpr int KT  = (MODE == 0) ? G_KT : (MODE == 1) ? U_KT : D_KT;
    constexpr int AST = (MODE == 2) ? DPAD : DIN;   // halves per A row

    extern __shared__ char smem[];
    const uint32_t sb = (uint32_t)__cvta_generic_to_shared(smem);

    const int tid = threadIdx.x, lane = tid & 31, wid = tid >> 5;
    const int wm = wid & 3, wn = wid >> 2;          // 4m x 2n warp grid
    const int grp = lane >> 2, tig = lane & 3;
    const int nt = blockIdx.x, row0 = blockIdx.y * BM;

    const uint32_t aBase = (uint32_t)((wm * 32 + (lane & 15)) * SROW + ((lane >> 4) << 4));
    const uint32_t bLane = (uint32_t)(((((lane >> 4) << 3) + (lane & 7)) * SROW) +
                                      (((lane >> 3) & 1) << 4));
    uint32_t bOff[4];
    #pragma unroll
    for (int p = 0; p < 4; ++p) {
        int nrow = (MODE == 1)
            ? ((p < 2) ? wn * 32 + p * 16 : 64 + wn * 32 + (p - 2) * 16)
            : wn * 64 + p * 16;
        bOff[p] = A_BYTES + (uint32_t)(nrow * SROW) + bLane;
    }

    const __half* Abase = (MODE == 0) ? g_xnorm + (size_t)row0 * DIN
                        : (MODE == 1) ? g_htnorm + (size_t)row0 * DH
                                      : g_act + (size_t)row0 * DPAD;
    const __half* Ahr = (MODE == 0)
        ? g_hr + (size_t)row0 * DH + ((nt >> 1) & 3) * HD : (const __half*)0;
    const __half* Bimg = (MODE == 0) ? g_Bg : (MODE == 1) ? g_Bup : g_Bd;

    auto loadTile = [&](int kt) {
        uint32_t stg = sb + (uint32_t)(kt & 3) * STAGE_BYTES;
        const __half* Asrc = (MODE == 0 && kt >= 32)
            ? Ahr + (kt - 32) * 32 : Abase + kt * 32;
        #pragma unroll
        for (int i = 0; i < 2; ++i) {
            int q = tid + i * THR, r = q >> 2, c = q & 3;
            cp16(stg + (uint32_t)(r * SROW + c * 16), Asrc + (size_t)r * AST + c * 8);
        }
        const __half* Bsrc = Bimg + ((size_t)nt * KT + kt) * 4096;
        #pragma unroll
        for (int i = 0; i < 2; ++i) {
            int q = tid + i * THR;
            cp16(stg + A_BYTES + (uint32_t)((q >> 2) * SROW + (q & 3) * 16), Bsrc + q * 8);
        }
    };

    float acc[2][8][4];
    #pragma unroll
    for (int mi = 0; mi < 2; ++mi)
        #pragma unroll
        for (int ni = 0; ni < 8; ++ni)
            #pragma unroll
            for (int q = 0; q < 4; ++q) acc[mi][ni][q] = 0.f;

    loadTile(0); CP_COMMIT;
    loadTile(1); CP_COMMIT;
    loadTile(2); CP_COMMIT;

    for (int t = 0; t < KT; ++t) {
        if (t <= KT - 3)      { CP_WAIT(2); }
        else if (t == KT - 2) { CP_WAIT(1); }
        else                  { CP_WAIT(0); }
        __syncthreads();
        if (t + 3 < KT) { loadTile(t + 3); CP_COMMIT; }

        uint32_t stg = sb + (uint32_t)(t & 3) * STAGE_BYTES;
        unsigned af[2][2][4], bf[2][8][2];
        #pragma unroll
        for (int ks = 0; ks < 2; ++ks) {
            uint32_t kb = (uint32_t)(ks * 32);
            LDSM4(af[ks][0], stg + aBase + kb);
            LDSM4(af[ks][1], stg + aBase + 16 * SROW + kb);
            LDSM4(&bf[ks][0][0], stg + bOff[0] + kb);
            LDSM4(&bf[ks][2][0], stg + bOff[1] + kb);
            LDSM4(&bf[ks][4][0], stg + bOff[2] + kb);
            LDSM4(&bf[ks][6][0], stg + bOff[3] + kb);
        }
        #pragma unroll
        for (int ks = 0; ks < 2; ++ks)
            #pragma unroll
            for (int mi = 0; mi < 2; ++mi)
                #pragma unroll
                for (int ni = 0; ni < 8; ++ni)
                    mma16(acc[mi][ni], af[ks][mi], bf[ks][ni]);
    }
    __syncthreads();

    if (MODE == 0) {
        #pragma unroll
        for (int mi = 0; mi < 2; ++mi) {
            int r = row0 + wm * 32 + mi * 16 + grp;
            #pragma unroll
            for (int ni = 0; ni < 8; ++ni) {
                int c = nt * 128 + wn * 64 + ni * 8 + tig * 2;
                float b0 = g_bias[c], b1 = g_bias[c + 1];
                *(__half2*)&g_gates[(size_t)r * GN + c] =
                    __floats2half2_rn(acc[mi][ni][0] + b0, acc[mi][ni][1] + b1);
                *(__half2*)&g_gates[(size_t)(r + 8) * GN + c] =
                    __floats2half2_rn(acc[mi][ni][2] + b0, acc[mi][ni][3] + b1);
            }
        }
    } else if (MODE == 2) {
        #pragma unroll
        for (int mi = 0; mi < 2; ++mi) {
            int r = row0 + wm * 32 + mi * 16 + grp;
            #pragma unroll
            for (int ni = 0; ni < 8; ++ni) {
                int c = nt * 128 + wn * 64 + ni * 8 + tig * 2;
                float b0 = e1[c], b1 = e1[c + 1];
                float2 x0 = *(const float2*)&e0[(size_t)r * DIN + c];
                float2 x1 = *(const float2*)&e0[(size_t)(r + 8) * DIN + c];
                float2 v0 = {acc[mi][ni][0] + b0 + x0.x, acc[mi][ni][1] + b1 + x0.y};
                float2 v1 = {acc[mi][ni][2] + b0 + x1.x, acc[mi][ni][3] + b1 + x1.y};
                *(float2*)&outp[(size_t)r * DIN + c]       = v0;
                *(float2*)&outp[(size_t)(r + 8) * DIN + c] = v1;
            }
        }
    } else {
        // MODE 1: acc[mi][j] = S, acc[mi][j+4] = G of the SAME output column
        #pragma unroll
        for (int mi = 0; mi < 2; ++mi) {
            int rb = row0 + wm * 32 + mi * 16 + grp;
            #pragma unroll
            for (int j = 0; j < 4; ++j) {
                int cc = nt * 64 + wn * 32 + j * 8 + tig * 2;
                #pragma unroll
                for (int h = 0; h < 2; ++h) {
                    int row = rb + h * 8;
                    #pragma unroll
                    for (int jj = 0; jj < 2; ++jj) {
                        int c2 = cc + jj;
                        if (c2 < DPAD) {
                            float v = 0.f;
                            if (c2 < DP) {
                                float sv = acc[mi][j][h * 2 + jj] + e0[c2];
                                float gv = acc[mi][j + 4][h * 2 + jj] + e0[c2 + DP];
                                float ge = 0.5f * gv * (1.f + erff(gv * 0.70710678118654752f));
                                v = sv * ge;
                            }
                            g_act[(size_t)row * DPAD + c2] = __float2half_rn(v);
                        }
                    }
                }
            }
        }
    }
}

// ---------------- launch ----------------
extern "C" void kernel_launch(void* const* d_in, const int* in_sizes, int n_in,
                              void* d_out, int out_size)
{
    const float* x      = (const float*)d_in[0];
    const float* h_prev = (const float*)d_in[1];
    const float* c_prev = (const float*)d_in[2];
    const float* n_prev = (const float*)d_in[3];
    const float* m_prev = (const float*)d_in[4];
    const float* ln_w   = (const float*)d_in[5];
    const float* ln_b   = (const float*)d_in[6];
    const float* Wz = (const float*)d_in[7];
    const float* bz = (const float*)d_in[8];
    const float* Wi = (const float*)d_in[9];
    const float* bi = (const float*)d_in[10];
    const float* Wf = (const float*)d_in[11];
    const float* bf = (const float*)d_in[12];
    const float* Wo = (const float*)d_in[13];
    const float* bo = (const float*)d_in[14];
    const float* Rz  = (const float*)d_in[15];
    const float* rbz = (const float*)d_in[16];
    const float* Ri  = (const float*)d_in[17];
    const float* rbi = (const float*)d_in[18];
    const float* Rf  = (const float*)d_in[19];
    const float* rbf = (const float*)d_in[20];
    const float* Ro  = (const float*)d_in[21];
    const float* rbo = (const float*)d_in[22];
    const float* gn_w = (const float*)d_in[23];
    const float* gn_b = (const float*)d_in[24];
    const float* Wup  = (const float*)d_in[25];
    const float* bup  = (const float*)d_in[26];
    const float* Wdown = (const float*)d_in[27];
    const float* bdown = (const float*)d_in[28];

    float* out  = (float*)d_out;
    float* y_o  = out;
    float* ht_o = out + (size_t)PLANE;
    float* ct_o = out + (size_t)2 * PLANE;
    float* nt_o = out + (size_t)3 * PLANE;
    float* mt_o = out + (size_t)4 * PLANE;

    cudaFuncSetAttribute(gemm_ls<0>, cudaFuncAttributeMaxDynamicSharedMemorySize, SMEMSZ);
    cudaFuncSetAttribute(gemm_ls<1>, cudaFuncAttributeMaxDynamicSharedMemorySize, SMEMSZ);
    cudaFuncSetAttribute(gemm_ls<2>, cudaFuncAttributeMaxDynamicSharedMemorySize, SMEMSZ);

    repack_gb<<<(G_NT * G_KT * 4096 + 255) / 256, 256>>>(
        Wz, Wi, Wf, Wo, Rz, Ri, Rf, Ro,
        bz, bi, bf, bo, rbz, rbi, rbf, rbo);
    lnh_kernel<<<BSZ + PLANE / 1024, 256>>>(x, ln_w, ln_b, h_prev);
    repack_ub<<<(U_NT * U_KT * 4096 + 255) / 256, 256>>>(Wup);

    gemm_ls<0><<<dim3(G_NT, BSZ / BM), THR, SMEMSZ>>>(nullptr, nullptr, nullptr);

    cell_kernel<<<BSZ * 4, 256>>>(c_prev, n_prev, m_prev, gn_w, gn_b,
                                  ht_o, ct_o, nt_o, mt_o);

    gemm_ls<1><<<dim3(U_NT, BSZ / BM), THR, SMEMSZ>>>(bup, nullptr, nullptr);

    repack_db<<<(D_NT * D_KT * 4096 + 255) / 256, 256>>>(Wdown);
    gemm_ls<2><<<dim3(D_NT, BSZ / BM), THR, SMEMSZ>>>(x, bdown, y_o);
}